// round 5
// baseline (speedup 1.0000x reference)
#include <cuda_runtime.h>
#include <math.h>

#define NLEV   16
#define NDENSE 12
#define NCONS  4
#define TSIZE  524288
#define HPRIME 2654435761u
#define HMASK  524287u
#define BLK    256

// Unified per-level params (dense levels hardcoded, hash levels from lengths).
struct LevelParams { float gs; int res; int n; int pad; };
__device__ LevelParams g_lp[NLEV];

__global__ void setup_kernel(const int* __restrict__ lengths, int L)
{
    if (threadIdx.x == 0 && blockIdx.x == 0) {
        // Dense resolutions: float32 np.power chain, margins all >> ulp error.
        const int rd[NDENSE] = {16,22,30,42,58,80,111,153,212,294,406,561};
        for (int i = 0; i < NDENSE; i++) {
            g_lp[i].res = rd[i];
            g_lp[i].gs  = (float)(2048.0 / (double)rd[i]);
            g_lp[i].n   = 0;
        }
        for (int i = 0; i < NCONS; i++) {
            int li  = (i < L) ? i : (L - 1);
            int len = lengths[li];                    // (res+1)^2
            int res = (int)(sqrt((double)len) + 0.5) - 1;
            g_lp[NDENSE + i].res = res;
            g_lp[NDENSE + i].n   = len;
            g_lp[NDENSE + i].gs  = (float)(2048.0 / (double)res);
        }
    }
}

// XLA:GPU emits approximate full-range division (div.full.f32) for f32 divide.
// Required for bit-exact bl = floor(x/gs) at cell boundaries.
__device__ __forceinline__ float div_full(float a, float b)
{
    float r;
    asm("div.full.f32 %0, %1, %2;" : "=f"(r) : "f"(a), "f"(b));
    return r;
}

// Exact replica of jnp.searchsorted(tk_row, 2h) -> where(k==n,0,k) -> tv[k].
// Only reached when a corner coordinate exceeds res (rounding edge case).
__device__ __forceinline__ int cons_lookup(const int* __restrict__ tk,
                                           const int* __restrict__ tv,
                                           long long rowoff, int n, unsigned h)
{
    int q  = 2 * (int)h;
    int lo = 0, hi = n;
    while (lo < hi) {
        int mid = (lo + hi) >> 1;
        if (__ldg(tk + rowoff + mid) < q) lo = mid + 1; else hi = mid;
    }
    if (lo == n) lo = 0;
    return __ldg(tv + rowoff + lo);
}

// 8 threads per point; lane role g = t&7 owns levels {2g, 2g+1}.
// g<6: all-dense (adjacent corner pairs -> LDG.128 trick); g>=6: all-hash.
// Lane's feats = contiguous 4-float slice -> exactly one STG.128 per thread.
__global__ __launch_bounds__(BLK)
void hashgrid_kernel(const float* __restrict__ x,
                     const float* __restrict__ tables,
                     const int*   __restrict__ tk,
                     const int*   __restrict__ tv,
                     int maxP,
                     float* __restrict__ out,
                     int npts)
{
    const int t = blockIdx.x * BLK + threadIdx.x;
    const int p = t >> 3;
    const int g = t & 7;
    const bool valid = (p < npts);
    const int  pl = valid ? p : (npts - 1);

    const float2 xv = __ldg((const float2*)x + pl);
    const float x0 = xv.x, x1 = xv.y;
    const size_t idxbase = (size_t)npts * 32;
    const int lvl0 = 2 * g;

    int   idxs[8];
    float w0s[2], w1s[2];

    // ---- phase 1: indices + weights for this lane's 2 levels ----
#pragma unroll
    for (int j = 0; j < 2; j++) {
        const int lvl = lvl0 + j;
        const LevelParams lp = g_lp[lvl];
        const int   res = lp.res;
        const float gs  = lp.gs;

        float q0  = div_full(x0, gs);
        float q1  = div_full(x1, gs);
        float b0f = floorf(q0), b1f = floorf(q1);
        int   b0  = (int)b0f,   b1  = (int)b1f;
        float mn0 = b0f * gs,   mn1 = b1f * gs;
        w0s[j] = __fdiv_rn(x0 - mn0, (mn0 + gs) - mn0);
        w1s[j] = __fdiv_rn(x1 - mn1, (mn1 + gs) - mn1);

        if (lvl < NDENSE) {
            int i00 = b0 * res + b1;
            idxs[4 * j + 0] = i00;
            idxs[4 * j + 1] = i00 + 1;
            idxs[4 * j + 2] = i00 + res;
            idxs[4 * j + 3] = i00 + res + 1;
        } else {
            unsigned g0 = (unsigned)b0, g1 = (unsigned)b1;
            unsigned h00 = (g0        ^ (g1        * HPRIME)) & HMASK;
            unsigned h01 = (g0        ^ ((g1 + 1u) * HPRIME)) & HMASK;
            unsigned h10 = ((g0 + 1u) ^ (g1        * HPRIME)) & HMASK;
            unsigned h11 = ((g0 + 1u) ^ ((g1 + 1u) * HPRIME)) & HMASK;

            if ((unsigned)b0 < (unsigned)res && (unsigned)b1 < (unsigned)res) {
                // All 4 corners present in table => searchsorted returns the hash.
                idxs[4 * j + 0] = (int)h00; idxs[4 * j + 1] = (int)h01;
                idxs[4 * j + 2] = (int)h10; idxs[4 * j + 3] = (int)h11;
            } else {
                int li = lvl - NDENSE;
                long long ro = (long long)li * maxP;
                int n = lp.n;
                idxs[4 * j + 0] = cons_lookup(tk, tv, ro, n, h00);
                idxs[4 * j + 1] = cons_lookup(tk, tv, ro, n, h01);
                idxs[4 * j + 2] = cons_lookup(tk, tv, ro, n, h10);
                idxs[4 * j + 3] = cons_lookup(tk, tv, ro, n, h11);
            }
        }
    }

    // ---- phase 2: gathers, issued back-to-back for MLP ----
    float2 e[8];
    if (g < 6) {
        // Dense: corner pairs (i00,i01) / (i10,i11) are adjacent 8B entries.
#pragma unroll
        for (int j = 0; j < 2; j++) {
            const int lvl = lvl0 + j;
            const float2* tb  = (const float2*)tables + (size_t)lvl * TSIZE;
            const float4* tb4 = (const float4*)tb;
#pragma unroll
            for (int pr = 0; pr < 2; pr++) {
                int ibase = idxs[4 * j + 2 * pr];
                float4 lo = __ldg(tb4 + (ibase >> 1));
                float2 hi = make_float2(0.f, 0.f);
                bool odd = (ibase & 1);
                if (odd) hi = __ldg(tb + ibase + 1);
                e[4 * j + 2 * pr]     = odd ? make_float2(lo.z, lo.w)
                                            : make_float2(lo.x, lo.y);
                e[4 * j + 2 * pr + 1] = odd ? hi : make_float2(lo.z, lo.w);
            }
        }
    } else {
        // Hash levels: 8 independent random corners.
#pragma unroll
        for (int j = 0; j < 2; j++) {
            const int lvl = lvl0 + j;
            const float2* tb = (const float2*)tables + (size_t)lvl * TSIZE;
#pragma unroll
            for (int k = 0; k < 4; k++)
                e[4 * j + k] = __ldg(tb + idxs[4 * j + k]);
        }
    }

    // ---- phase 3: idx stores (overlap gather latency) ----
    if (valid) {
#pragma unroll
        for (int j = 0; j < 2; j++) {
            const int lvl = lvl0 + j;
            float4 v = make_float4((float)idxs[4 * j + 0], (float)idxs[4 * j + 1],
                                   (float)idxs[4 * j + 2], (float)idxs[4 * j + 3]);
            __stcs((float4*)(out + idxbase + ((size_t)lvl * npts + p) * 4), v);
        }
    }

    // ---- phase 4: interpolate + one contiguous STG.128 feat store ----
    if (valid) {
        float f[4];
#pragma unroll
        for (int j = 0; j < 2; j++) {
            float w0 = w0s[j], w1 = w1s[j];
            float om0 = 1.0f - w0, om1 = 1.0f - w1;
            float2 e00 = e[4 * j + 0], e01 = e[4 * j + 1];
            float2 e10 = e[4 * j + 2], e11 = e[4 * j + 3];
            float c0x = e00.x * om1 + e01.x * w1;
            float c1x = e10.x * om1 + e11.x * w1;
            float c0y = e00.y * om1 + e01.y * w1;
            float c1y = e10.y * om1 + e11.y * w1;
            f[2 * j]     = c0x * om0 + c1x * w0;
            f[2 * j + 1] = c0y * om0 + c1y * w0;
        }
        __stcs((float4*)(out + (size_t)p * 32 + 4 * g),
               make_float4(f[0], f[1], f[2], f[3]));
    }
}

extern "C" void kernel_launch(void* const* d_in, const int* in_sizes, int n_in,
                              void* d_out, int out_size)
{
    const float* x       = (const float*)d_in[0];
    const float* tables  = (const float*)d_in[1];
    const int*   tk      = (const int*)d_in[2];
    const int*   tv      = (const int*)d_in[3];
    const int*   lengths = (const int*)d_in[4];

    int L    = in_sizes[4];
    int maxP = in_sizes[2] / (L > 0 ? L : 1);
    int npts = in_sizes[0] / 2;

    setup_kernel<<<1, 32>>>(lengths, L);

    long long nthreads = 8LL * npts;
    int blocks = (int)((nthreads + BLK - 1) / BLK);
    hashgrid_kernel<<<blocks, BLK>>>(x, tables, tk, tv, maxP, (float*)d_out, npts);
}